// round 17
// baseline (speedup 1.0000x reference)
#include <cuda_runtime.h>
#include <cuda_fp16.h>
#include <cstdint>
#include <math.h>

#define D_MODEL 2048
#define N_EXP   64
#define TM      64                  // tokens per CTA
#define KB      64                  // K elems per stage
#define NSTG    (D_MODEL / KB)      // 32
#define THREADS 256
#define WPITCH  36                  // uint2 per W row (bank-perm)
#define LPITCH  68

#define XBUF_BYTES 16384            // 64 rows x 256B ({hi64,lo64} pairs)
#define WBUF_BYTES 18432            // 64 rows x 288B
#define WOFF      (2 * XBUF_BYTES)          // 32768
#define BIAS_OFF  (WOFF + 2 * WBUF_BYTES)   // 69632
#define SMEM_DYN  (BIAS_OFF + 256)

#define RINV12 (1.0f / 4096.0f)

// packed W: per k-pair {f16x2(hi*64), f16x2(lo*64)}
__device__ uint2 g_wpk[N_EXP * (D_MODEL / 2)];

__device__ __forceinline__ uint32_t smem_u32(const void* p) {
    uint32_t a;
    asm("{ .reg .u64 t; cvta.to.shared.u64 t, %1; cvt.u32.u64 %0, t; }" : "=r"(a) : "l"(p));
    return a;
}
__device__ __forceinline__ void cp16(uint32_t dst, const void* src) {
    asm volatile("cp.async.cg.shared.global [%0], [%1], 16;" :: "r"(dst), "l"(src) : "memory");
}
#define CP_COMMIT() asm volatile("cp.async.commit_group;" ::: "memory")
#define CP_WAIT(n)  asm volatile("cp.async.wait_group %0;" :: "n"(n) : "memory")

__device__ __forceinline__ uint32_t h2u(half2 h) {
    return *reinterpret_cast<uint32_t*>(&h);
}
__device__ __forceinline__ void mma16_dc(float* d,
                                         uint32_t a0, uint32_t a1, uint32_t a2, uint32_t a3,
                                         uint32_t b0, uint32_t b1) {
    asm volatile("mma.sync.aligned.m16n8k16.row.col.f32.f16.f16.f32 "
                 "{%0,%1,%2,%3},{%4,%5,%6,%7},{%8,%9},{%10,%11,%12,%13};"
                 : "=f"(d[0]), "=f"(d[1]), "=f"(d[2]), "=f"(d[3])
                 : "r"(a0), "r"(a1), "r"(a2), "r"(a3), "r"(b0), "r"(b1),
                   "f"(0.0f), "f"(0.0f), "f"(0.0f), "f"(0.0f));
}
__device__ __forceinline__ void mma16_acc(float* d,
                                          uint32_t a0, uint32_t a1, uint32_t a2, uint32_t a3,
                                          uint32_t b0, uint32_t b1) {
    asm volatile("mma.sync.aligned.m16n8k16.row.col.f32.f16.f16.f32 "
                 "{%0,%1,%2,%3},{%4,%5,%6,%7},{%8,%9},{%0,%1,%2,%3};"
                 : "+f"(d[0]), "+f"(d[1]), "+f"(d[2]), "+f"(d[3])
                 : "r"(a0), "r"(a1), "r"(a2), "r"(a3), "r"(b0), "r"(b1));
}

// split v -> {hi*64, lo*64} fp16 pair (hi*64 exact; residual scaled)
__device__ __forceinline__ uint2 split2(float a, float b) {
    const half2 sc64 = __halves2half2(__float2half_rn(64.0f), __float2half_rn(64.0f));
    half2 h = __floats2half2_rn(a, b);
    half2 h64 = __hmul2(h, sc64);
    float2 hf = __half22float2(h);
    half2 l64 = __floats2half2_rn((a - hf.x) * 64.0f, (b - hf.y) * 64.0f);
    return make_uint2(h2u(h64), h2u(l64));
}

// ---- prep: split W into {hi*64, lo*64} fp16 pairs ----
__global__ void split_w(const float* __restrict__ W) {
    const int i = blockIdx.x * 256 + threadIdx.x;          // pair index
    if (i < N_EXP * (D_MODEL / 2)) {
        g_wpk[i] = split2(W[2 * i], W[2 * i + 1]);
    }
}

__global__ __launch_bounds__(THREADS, 3)
void router_hmma(const float* __restrict__ x,
                 const float* __restrict__ bias, float* __restrict__ out, int T)
{
    extern __shared__ float smf[];
    char* smc = (char*)smf;
    const uint32_t sbase = smem_u32(smf);

    const int tid  = threadIdx.x;
    const int wid  = tid >> 5;
    const int lane = tid & 31;
    const int g    = lane >> 2;
    const int c    = lane & 3;
    const int wm   = (wid & 3) * 16;     // warp's 16 tokens
    const int we   = (wid >> 2) * 32;    // warp's 32 experts
    const int t0   = blockIdx.x * TM;
    const int lrow = tid >> 2;           // loader row 0..63
    const int lcb  = tid & 3;

    if (tid < N_EXP) smf[BIAS_OFF / 4 + tid] = bias[tid];

    auto loadW = [&](int s, int buf) {
        const uint32_t dst0 = sbase + WOFF + (uint32_t)buf * WBUF_BYTES
                            + (uint32_t)lrow * (WPITCH * 8) + lcb * 64;
        const uint2* src0 = g_wpk + (size_t)lrow * (D_MODEL / 2) + (s * KB >> 1) + lcb * 8;
#pragma unroll
        for (int i = 0; i < 4; ++i) cp16(dst0 + i * 16, src0 + i * 2);
    };
    auto ldgX = [&](int s, float4* xr) {
        const float* src = x + (size_t)(t0 + lrow) * D_MODEL + s * KB + lcb * 4;
#pragma unroll
        for (int i = 0; i < 4; ++i)
            xr[i] = *reinterpret_cast<const float4*>(src + i * 16);
    };
    auto stsX = [&](const float4* xr, int buf) {
        char* xb = smc + buf * XBUF_BYTES + lrow * 256;
        const int sw = (lrow & 3) << 2;
#pragma unroll
        for (int i = 0; i < 4; ++i) {
            uint2 u0 = split2(xr[i].x, xr[i].y);
            uint2 u1 = split2(xr[i].z, xr[i].w);
            const int p = i * 8 + lcb * 2;           // k-pair index (even)
            *reinterpret_cast<uint4*>(xb + ((p ^ sw) << 3)) =
                make_uint4(u0.x, u0.y, u1.x, u1.y);
        }
    };

    float master[4][4];
    float stageC[4][4];
#pragma unroll
    for (int nb = 0; nb < 4; ++nb)
#pragma unroll
        for (int q = 0; q < 4; ++q) master[nb][q] = 0.0f;

    float4 xr[4];
    ldgX(0, xr);
    loadW(0, 0); CP_COMMIT();
    loadW(1, 1); CP_COMMIT();
    stsX(xr, 0);
    ldgX(1, xr);

    const int swz = (g & 3) << 2;

#pragma unroll 1
    for (int s = 0; s < NSTG; ++s) {
        if (s == NSTG - 1) { CP_WAIT(0); } else { CP_WAIT(1); }
        __syncthreads();

        if (s + 1 < NSTG) stsX(xr, (s + 1) & 1);

        const char* xb = smc + (s & 1) * XBUF_BYTES;
        const uint2* wb = (const uint2*)(smc + WOFF + (s & 1) * WBUF_BYTES);

#pragma unroll
        for (int ch = 0; ch < 4; ++ch) {
            uint32_t AH[4], AL[4];
#pragma unroll
            for (int q = 0; q < 4; ++q) {
                const int row = wm + g + (q & 1) * 8;
                const int p   = ch * 8 + c + ((q >> 1) * 4);
                const uint2 u = *reinterpret_cast<const uint2*>(
                    xb + row * 256 + ((p ^ swz) << 3));
                AH[q] = u.x; AL[q] = u.y;
            }
#pragma unroll
            for (int nb = 0; nb < 4; ++nb) {
                const int base = (we + nb * 8 + g) * WPITCH + ch * 8 + c;
                const uint2 q0 = wb[base];
                const uint2 q1 = wb[base + 4];
                float* sc = stageC[nb];
                if (ch == 0) {
                    mma16_dc (sc, AH[0], AH[1], AH[2], AH[3], q0.x, q1.x);
                } else {
                    mma16_acc(sc, AH[0], AH[1], AH[2], AH[3], q0.x, q1.x);
                }
                mma16_acc(sc, AH[0], AH[1], AH[2], AH[3], q0.y, q1.y);
                mma16_acc(sc, AL[0], AL[1], AL[2], AL[3], q0.x, q1.x);
            }
        }
        // fold (scale 4096 -> unit)
#pragma unroll
        for (int nb = 0; nb < 4; ++nb)
#pragma unroll
            for (int q = 0; q < 4; ++q)
                master[nb][q] = fmaf(stageC[nb][q], RINV12, master[nb][q]);

        if (s + 2 < NSTG) ldgX(s + 2, xr);
        __syncthreads();
        if (s + 2 < NSTG) { loadW(s + 2, s & 1); CP_COMMIT(); }
    }

    // ---- epilogue: logits to smem, top-2 + softmax ----
    float* logits = smf;            // 64 x LPITCH floats = 17408 B (xbuf region)
#pragma unroll
    for (int nb = 0; nb < 4; ++nb)
#pragma unroll
        for (int q = 0; q < 4; ++q) {
            const int row = wm + g + ((q >> 1) * 8);
            const int col = we + nb * 8 + 2 * c + (q & 1);
            logits[row * LPITCH + col] = master[nb][q];
        }
    __syncthreads();

    if (tid < TM) {
        const float* lrow2  = logits + tid * LPITCH;
        const float* bias_s = smf + BIAS_OFF / 4;
        float m1 = -INFINITY, m2 = -INFINITY;
        int   i1 = 0,         i2 = 0;
        float l[64];
#pragma unroll 8
        for (int e = 0; e < N_EXP; ++e) {
            l[e] = lrow2[e] + bias_s[e];
            const float v = l[e];
            if (v > m1) { m2 = m1; i2 = i1; m1 = v; i1 = e; }
            else if (v > m2) { m2 = v; i2 = e; }
        }
        float ssum = 0.0f;
#pragma unroll 8
        for (int e = 0; e < N_EXP; ++e) ssum += __expf(l[e] - m1);
        const float inv = 1.0f / ssum;

        const int tg = t0 + tid;
        out[2 * tg + 0] = (float)i1;
        out[2 * tg + 1] = (float)i2;
        out[(size_t)2 * T + 2 * tg + 0] = inv;
        out[(size_t)2 * T + 2 * tg + 1] = __expf(m2 - m1) * inv;
    }
}

extern "C" void kernel_launch(void* const* d_in, const int* in_sizes, int n_in,
                              void* d_out, int out_size)
{
    const float* x = (const float*)d_in[0];
    const float* W = (const float*)d_in[1];
    const float* b = (const float*)d_in[2];
    float* out = (float*)d_out;

    const int T = in_sizes[0] / D_MODEL;   // 32768
    static int attr_done = 0;
    if (!attr_done) {
        cudaFuncSetAttribute(router_hmma, cudaFuncAttributeMaxDynamicSharedMemorySize, SMEM_DYN);
        attr_done = 1;
    }
    split_w<<<(N_EXP * (D_MODEL / 2) + 255) / 256, 256>>>(W);
    router_hmma<<<T / TM, THREADS, SMEM_DYN>>>(x, b, out, T);
}